// round 2
// baseline (speedup 1.0000x reference)
#include <cuda_runtime.h>

// Polyphase upsample-by-2 + 10001-tap FIR (full conv), fp32.
// out[b, 2p]   = sum_q w[2q]   * x[b, p-q],  q in [0,5000]
// out[b, 2p+1] = sum_q w[2q+1] * x[b, p-q],  q in [0,4999]
// Both phases share x reads; tap pairs (w[2q], w[2q+1]) are contiguous in w,
// so we accumulate both with one packed fma.rn.f32x2 per (r, q).

#define TNUM 256
#define RPT  8
#define TILE_P (TNUM * RPT)     // 2048 p-positions per block
#define NQ   5008               // taps per phase padded to multiple of 8
#define PAD  NQ
#define LEN  262144             // L
#define QLEN 10001              // filter length
#define NPAIR 267144            // number of (even,odd) output pairs per row = L + (Q-1)/2
#define OUTW 534288             // output row length = 2*NPAIR

#define XS_ELEMS (TILE_P + PAD)       // 7056 floats
#define WS_ELEMS (2 * NQ)             // 10016 floats (interleaved pairs, zero padded)
#define SMEM_BYTES ((XS_ELEMS + WS_ELEMS) * 4)   // 68288 bytes

__global__ __launch_bounds__(TNUM) void upfir2_kernel(
    const float* __restrict__ x,
    const float* __restrict__ w,
    float* __restrict__ out)
{
    extern __shared__ float sm[];
    float* xs = sm;              // x tile: xs[j] = x[p0 - PAD + j]
    float* ws = sm + XS_ELEMS;   // tap pairs, zero-padded

    const int t  = threadIdx.x;
    const int p0 = blockIdx.x * TILE_P;
    const int b  = blockIdx.y;
    const float* xb = x + (size_t)b * LEN;

    // Stage x tile (zero-pad out-of-range)
    for (int j = t; j < XS_ELEMS; j += TNUM) {
        int g = p0 - PAD + j;
        xs[j] = (g >= 0 && g < LEN) ? __ldg(xb + g) : 0.0f;
    }
    // Stage filter taps (interleaved pairs as-is), zero pad to 2*NQ
    for (int j = t; j < WS_ELEMS; j += TNUM) {
        ws[j] = (j < QLEN) ? __ldg(w + j) : 0.0f;
    }
    __syncthreads();

    // Packed accumulators: low lane = even phase, high lane = odd phase
    unsigned long long acc[RPT];
    unsigned long long xx[RPT];   // duplicated x value in both lanes
#pragma unroll
    for (int r = 0; r < RPT; ++r) acc[r] = 0ull;

    const int lb = t * RPT + PAD;   // local index of x[pt] in xs
#pragma unroll
    for (int r = 0; r < RPT; ++r) {
        float v = xs[lb + r];
        asm("mov.b64 %0, {%1, %1};" : "=l"(xx[r]) : "f"(v));
    }

    const unsigned long long* wsp =
        reinterpret_cast<const unsigned long long*>(ws);

#pragma unroll 2
    for (int q0 = 0; q0 < NQ; q0 += 4) {
        // next 4 sliding-window entries, descending use: xs[lb-q0-4 .. lb-q0-1]
        float4 xn = *reinterpret_cast<const float4*>(xs + lb - q0 - 4);
        float nx0 = xn.w, nx1 = xn.z, nx2 = xn.y, nx3 = xn.x;
#pragma unroll
        for (int u = 0; u < 4; ++u) {
            unsigned long long wq = wsp[q0 + u];   // (w[2q], w[2q+1]) broadcast
#pragma unroll
            for (int r = 0; r < RPT; ++r)
                asm("fma.rn.f32x2 %0, %1, %2, %0;"
                    : "+l"(acc[r]) : "l"(wq), "l"(xx[r]));
            // slide window: xx[r] <- xx[r-1]; xx[0] <- x[pt - (q+1)]
#pragma unroll
            for (int r = RPT - 1; r >= 1; --r) xx[r] = xx[r - 1];
            float nv = (u == 0) ? nx0 : (u == 1) ? nx1 : (u == 2) ? nx2 : nx3;
            asm("mov.b64 %0, {%1, %1};" : "=l"(xx[0]) : "f"(nv));
        }
    }

    // Store: acc[r] low = out[2p], high = out[2p+1] -> one float2
    float2* ob = reinterpret_cast<float2*>(out + (size_t)b * OUTW);
    const int pt = p0 + t * RPT;
#pragma unroll
    for (int r = 0; r < RPT; ++r) {
        int p = pt + r;
        if (p < NPAIR) ob[p] = *reinterpret_cast<float2*>(&acc[r]);
    }
}

extern "C" void kernel_launch(void* const* d_in, const int* in_sizes, int n_in,
                              void* d_out, int out_size)
{
    const float* x = (const float*)d_in[0];
    const float* w = (const float*)d_in[1];
    float* out = (float*)d_out;

    cudaFuncSetAttribute(upfir2_kernel,
                         cudaFuncAttributeMaxDynamicSharedMemorySize,
                         SMEM_BYTES);

    dim3 grid((NPAIR + TILE_P - 1) / TILE_P, 32);   // (131, 32)
    upfir2_kernel<<<grid, TNUM, SMEM_BYTES>>>(x, w, out);
}

// round 5
// speedup vs baseline: 7.1704x; 7.1704x over previous
#include <cuda_runtime.h>
#include <math.h>

// Overlap-save FFT convolution for upsample-by-2 + 10001-tap FIR.
//
// Polyphase: out[b,2p]   = (x_b * we)[p],  we[q] = w[2q],   q in [0,5000]
//            out[b,2p+1] = (x_b * wo)[p],  wo[q] = w[2q+1], q in [0,4999]
// Two-for-one: z = x_b + i*x_{b+1};  ifft(fft(z) .* Wf) = conv_b + i*conv_{b+1}
// (filter real). One fwd FFT + two (cmul + inv FFT) per segment per row pair.

#define LEN    262144
#define QLEN   10001
#define NPAIR  267144           // L + (Q-1)/2
#define OUTW   534288
#define NROWS  32

#define NF     8192             // FFT length
#define LOG2NF 13
#define HALF   (NF/2)           // 4096
#define TAPS_E 5001
#define TAPS_O 5000
#define HOP    (NF - 5000)      // 3192 valid outputs per segment
#define NSEG   ((NPAIR + HOP - 1) / HOP)   // 84

#define THREADS 512

// Scratch (static device globals — no allocation)
__device__ float2 g_tw[HALF];       // exp(-2*pi*i*k/NF)
__device__ float2 g_WF[2][NF];      // spectra of even/odd phase filters

// ---------------------------------------------------------------------------
// In-SMEM radix-2 Stockham DIF FFT, natural order in/out, ping-pong a<->b.
// Returns pointer to the buffer holding the result (13 stages -> b).
// ---------------------------------------------------------------------------
__device__ __forceinline__ float2* fft8k(float2* a, float2* b,
                                         int tid, int nthr)
{
    float2* cur = a;
    float2* nxt = b;
    int s = 1;
#pragma unroll 1
    for (int st = 0; st < LOG2NF; ++st) {
#pragma unroll
        for (int i = tid; i < HALF; i += THREADS) {
            int k = i & ~(s - 1);            // twiddle index = p*s
            float2 u = cur[i];
            float2 v = cur[i + HALF];
            float2 w = g_tw[k];
            float tx = u.x - v.x;
            float ty = u.y - v.y;
            float2 y1 = make_float2(u.x + v.x, u.y + v.y);
            float2 y2 = make_float2(fmaf(tx, w.x, -ty * w.y),
                                    fmaf(tx, w.y,  ty * w.x));
            int j = i + k;                   // = q + s*2p
            nxt[j]     = y1;
            nxt[j + s] = y2;
        }
        __syncthreads();
        float2* tmp = cur; cur = nxt; nxt = tmp;
        s <<= 1;
    }
    return cur;
}

// ---------------------------------------------------------------------------
// Setup kernel 1: twiddle table (fp64-accurate)
// ---------------------------------------------------------------------------
__global__ void twiddle_kernel()
{
    int k = blockIdx.x * blockDim.x + threadIdx.x;
    if (k < HALF) {
        double a = -2.0 * 3.14159265358979323846 * (double)k / (double)NF;
        g_tw[k] = make_float2((float)cos(a), (float)sin(a));
    }
}

// ---------------------------------------------------------------------------
// Setup kernel 2: filter phase spectra (one CTA per phase)
// ---------------------------------------------------------------------------
__global__ __launch_bounds__(THREADS) void filter_fft_kernel(
    const float* __restrict__ w)
{
    extern __shared__ float2 smf[];
    float2* A  = smf;
    float2* Bf = smf + NF;
    int ph  = blockIdx.x;            // 0 = even taps, 1 = odd taps
    int tid = threadIdx.x;
    int ntaps = ph ? TAPS_O : TAPS_E;
    for (int j = tid; j < NF; j += THREADS) {
        float v = (j < ntaps) ? w[2 * j + ph] : 0.0f;
        A[j] = make_float2(v, 0.0f);
    }
    __syncthreads();
    float2* R = fft8k(A, Bf, tid, THREADS);
    for (int j = tid; j < NF; j += THREADS)
        g_WF[ph][j] = R[j];
}

// ---------------------------------------------------------------------------
// Main: one CTA per (segment, row-pair)
// ---------------------------------------------------------------------------
__global__ __launch_bounds__(THREADS) void upfir_fft_kernel(
    const float* __restrict__ x, float* __restrict__ out)
{
    extern __shared__ float2 sm[];
    float2* A  = sm;            // ping
    float2* Bf = sm + NF;       // pong (holds Z after fwd FFT)
    float2* C  = sm + 2 * NF;   // cmul staging

    int tid = threadIdx.x;
    int seg = blockIdx.x;
    int rp  = blockIdx.y;

    const float* x0 = x + (size_t)(2 * rp) * LEN;
    const float* x1 = x0 + LEN;
    int p_start = seg * HOP;
    int base    = p_start - 5000;

    // Load packed segment (zero-padded)
    for (int j = tid; j < NF; j += THREADS) {
        int g = base + j;
        bool ok = (g >= 0) && (g < LEN);
        float re = ok ? __ldg(x0 + g) : 0.0f;
        float im = ok ? __ldg(x1 + g) : 0.0f;
        A[j] = make_float2(re, im);
    }
    __syncthreads();

    float2* Z = fft8k(A, Bf, tid, THREADS);          // Z = Bf
    float2* S = (Z == A) ? Bf : A;                   // scratch = A

    const float inv = 1.0f / (float)NF;
    float* ob0 = out + (size_t)(2 * rp) * OUTW;
    float* ob1 = ob0 + OUTW;

#pragma unroll 1
    for (int ph = 0; ph < 2; ++ph) {
        // C = conj(Z .* WF[ph])   (conj folds the inverse transform)
        for (int j = tid; j < NF; j += THREADS) {
            float2 z = Z[j];
            float2 w = g_WF[ph][j];
            C[j] = make_float2(fmaf(z.x, w.x, -z.y * w.y),
                               -fmaf(z.x, w.y,  z.y * w.x));
        }
        __syncthreads();

        float2* R = fft8k(C, S, tid, THREADS);       // R = S (=A), Z intact

        // result = conj(R)/NF : re -> row 2rp, -im -> row 2rp+1
        for (int t = tid; t < HOP; t += THREADS) {
            int p = p_start + t;
            if (p < NPAIR) {
                float2 r = R[5000 + t];
                ob0[2 * p + ph] =  r.x * inv;
                ob1[2 * p + ph] = -r.y * inv;
            }
        }
        __syncthreads();   // protect S before next phase's FFT overwrites it
    }
}

// ---------------------------------------------------------------------------
extern "C" void kernel_launch(void* const* d_in, const int* in_sizes, int n_in,
                              void* d_out, int out_size)
{
    const float* x = (const float*)d_in[0];
    const float* w = (const float*)d_in[1];
    float* out = (float*)d_out;

    static bool attr_done = false;
    if (!attr_done) {
        cudaFuncSetAttribute(filter_fft_kernel,
                             cudaFuncAttributeMaxDynamicSharedMemorySize,
                             2 * NF * (int)sizeof(float2));
        cudaFuncSetAttribute(upfir_fft_kernel,
                             cudaFuncAttributeMaxDynamicSharedMemorySize,
                             3 * NF * (int)sizeof(float2));
        attr_done = true;
    }

    twiddle_kernel<<<(HALF + 255) / 256, 256>>>();
    filter_fft_kernel<<<2, THREADS, 2 * NF * sizeof(float2)>>>(w);

    dim3 grid(NSEG, NROWS / 2);   // (84, 16)
    upfir_fft_kernel<<<grid, THREADS, 3 * NF * sizeof(float2)>>>(x, out);
}